// round 7
// baseline (speedup 1.0000x reference)
#include <cuda_runtime.h>
#include <cstdint>

// GCN via mma.sync tf32 + ldmatrix + cp.async (arch-stable PTX; tcgen05 is
// sm_103a-gated and the harness targets base sm_103).
// R6: CTA tile 160x128 (warp tile 80x64, 4 warps, occ 2), 3-stage cp.async
// pipeline, SW128 swizzle, fp32 accumulate.
//  - RNDA template: in-register RNA tf32 rounding of A frags (+0x1000 before
//    HMMA truncation) ONLY for kernels whose A is raw (G layers, F1).
//  - A-fragments software-pipelined across the 4 k-substeps (double buffer)
//    so LDSM + IADD latency hides under HMMA issue.
//  - Weight transposes batched into 2 launches (also puts ncu's sampled
//    launch on G2).

#define NNODES 10000
#define KT 32
#define A_BYTES 20480               // 160 x 32 fp32
#define STAGE_BYTES 36864           // A 20KB + B 16KB
#define SMEM_TOTAL (3 * STAGE_BYTES)

__device__ float g_bufA[(size_t)NNODES * 1024];
__device__ float g_bufB[(size_t)NNODES * 1024];
__device__ float g_wts[1310720];
#define O_W1T 0
#define O_W2T 262144
#define O_W3T 524288
#define O_WFT 1048576

__device__ __forceinline__ uint32_t smem_u32(const void* p) {
    uint32_t a;
    asm("{ .reg .u64 t; cvta.to.shared.u64 t, %1; cvt.u32.u64 %0, t; }"
        : "=r"(a) : "l"(p));
    return a;
}
// full RNA round to tf32 (for data written to memory)
__device__ __forceinline__ float rtf32(float v) {
    return __uint_as_float((__float_as_uint(v) + 0x1000u) & 0xFFFFE000u);
}

__device__ __forceinline__ void cpa16(uint32_t dst, const float* src, int bytes) {
    asm volatile("cp.async.cg.shared.global [%0], [%1], 16, %2;"
                 :: "r"(dst), "l"(src), "r"(bytes) : "memory");
}
#define CP_COMMIT() asm volatile("cp.async.commit_group;" ::: "memory")
#define CP_WAIT1()  asm volatile("cp.async.wait_group 1;" ::: "memory")
#define CP_WAIT0()  asm volatile("cp.async.wait_group 0;" ::: "memory")

__device__ __forceinline__ void ldsm4(uint32_t* r, uint32_t a) {
    asm volatile("ldmatrix.sync.aligned.m8n8.x4.shared.b16 {%0,%1,%2,%3}, [%4];"
                 : "=r"(r[0]), "=r"(r[1]), "=r"(r[2]), "=r"(r[3]) : "r"(a));
}
__device__ __forceinline__ void ldsm2(uint32_t* r, uint32_t a) {
    asm volatile("ldmatrix.sync.aligned.m8n8.x2.shared.b16 {%0,%1}, [%2];"
                 : "=r"(r[0]), "=r"(r[1]) : "r"(a));
}
__device__ __forceinline__ void mma8(float* c, const uint32_t* a, const uint32_t* b) {
    asm volatile("mma.sync.aligned.m16n8k8.row.col.f32.tf32.tf32.f32 "
                 "{%0,%1,%2,%3}, {%4,%5,%6,%7}, {%8,%9}, {%0,%1,%2,%3};"
                 : "+f"(c[0]), "+f"(c[1]), "+f"(c[2]), "+f"(c[3])
                 : "r"(a[0]), "r"(a[1]), "r"(a[2]), "r"(a[3]),
                   "r"(b[0]), "r"(b[1]));
}

// C = A[M,K] @ B_nk[N,K]^T ; A,B row-major, leading dim K.
// TRANS: write C^T [N,M]; else C [M,N]. CTA tile 160x128.
// RNDA: RNA-round A fragments in-register (A raw fp32 in memory).
// B must always be tf32 in memory (weights: prep; activations: epilogues).
template <int TRANS, int BIAS, int RELU, int ROUND, int RNDA>
__global__ void __launch_bounds__(128, 2)
tc_gemm(const float* __restrict__ A, const float* __restrict__ B,
        const float* __restrict__ bias, float* __restrict__ C,
        int M, int N, int K) {
    extern __shared__ char smem[];
    const uint32_t sb = smem_u32(smem);
    const int tid = threadIdx.x;
    const int lane = tid & 31, w = tid >> 5;
    const int warp_m = (w & 1) * 80, warp_n = (w >> 1) * 64;
    const int rowBase = blockIdx.y * 160, colBase = blockIdx.x * 128;

    // ---- loader: chunk i covers row (tid>>3)+16i, cols (tid&7)*4..+3
    const int ldr = tid >> 3;        // 0..15
    const int ldc4 = (tid & 7) * 4;  // col offset (floats)
    const uint32_t swz = (uint32_t)(((tid & 7) ^ (ldr & 7)) * 16);
    const uint32_t dstBase = (uint32_t)(ldr * 128) + swz;
    const float* aBase = A + (size_t)(rowBase + ldr) * K + ldc4;
    const float* bBase = B + (size_t)(colBase + ldr) * K + ldc4;
    const size_t K16 = (size_t)K * 16;

    const int nc = (K + KT - 1) / KT;

    auto issue = [&](int c) {
        const uint32_t st = sb + (uint32_t)(c % 3) * STAGE_BYTES;
        const int k0 = c * KT;
        const bool kok = (k0 + ldc4) < K;
#pragma unroll
        for (int i = 0; i < 10; i++) {  // A: 160 rows
            bool v = kok && (rowBase + ldr + 16 * i) < M;
            cpa16(st + dstBase + (uint32_t)i * 2048,
                  aBase + k0 + (size_t)i * K16, v ? 16 : 0);
        }
#pragma unroll
        for (int i = 0; i < 8; i++) {   // B: 128 rows
            bool v = kok && (colBase + ldr + 16 * i) < N;
            cpa16(st + A_BYTES + dstBase + (uint32_t)i * 2048,
                  bBase + k0 + (size_t)i * K16, v ? 16 : 0);
        }
        CP_COMMIT();
    };

    issue(0);
    issue(1);

    // ---- fragment addressing (SW128, ldmatrix) ----
    const int l8 = lane & 7;
    const int l16 = lane & 15;
    const uint32_t aLdRow = (uint32_t)(warp_m + l8 + ((lane >> 3) & 1) * 8) * 128;
    const uint32_t bLdRow = (uint32_t)(warp_n + (l16 & 7)) * 128;
    uint32_t aChunk[4], bChunk[4];
#pragma unroll
    for (int s = 0; s < 4; s++) {
        aChunk[s] = (uint32_t)(((s * 2 + (lane >> 4)) ^ l8) * 16);
        bChunk[s] = (uint32_t)(((s * 2 + (l16 >> 3)) ^ (l16 & 7)) * 16);
    }

    float cr[5][8][4];
#pragma unroll
    for (int mt = 0; mt < 5; mt++)
#pragma unroll
        for (int nt = 0; nt < 8; nt++)
#pragma unroll
            for (int r = 0; r < 4; r++) cr[mt][nt][r] = 0.f;

    for (int c = 0; c < nc; c++) {
        CP_WAIT1();
        __syncthreads();
        if (c + 2 < nc) issue(c + 2); else CP_COMMIT();

        const uint32_t sA = sb + (uint32_t)(c % 3) * STAGE_BYTES;
        const uint32_t sB = sA + A_BYTES;

        // A fragments double-buffered across k-substeps
        uint32_t a[2][5][4], b[8][2];
#pragma unroll
        for (int mt = 0; mt < 5; mt++) {
            ldsm4(a[0][mt], sA + aLdRow + mt * 2048 + aChunk[0]);
            if (RNDA) {
#pragma unroll
                for (int r = 0; r < 4; r++) a[0][mt][r] += 0x1000u;
            }
        }
#pragma unroll
        for (int s = 0; s < 4; s++) {
            const int cur = s & 1, nxt = cur ^ 1;
            if (s < 3) {  // prefetch A for next substep (hides LDSM+IADD)
#pragma unroll
                for (int mt = 0; mt < 5; mt++) {
                    ldsm4(a[nxt][mt], sA + aLdRow + mt * 2048 + aChunk[s + 1]);
                    if (RNDA) {
#pragma unroll
                        for (int r = 0; r < 4; r++) a[nxt][mt][r] += 0x1000u;
                    }
                }
            }
#pragma unroll
            for (int nt = 0; nt < 8; nt++)
                ldsm2(b[nt], sB + bLdRow + nt * 1024 + bChunk[s]);
#pragma unroll
            for (int mt = 0; mt < 5; mt++)
#pragma unroll
                for (int nt = 0; nt < 8; nt++)
                    mma8(cr[mt][nt], a[cur][mt], b[nt]);
        }
    }
    CP_WAIT0();

    // ---- epilogue ----
    const int g = lane >> 2, t = lane & 3;
#pragma unroll
    for (int mt = 0; mt < 5; mt++) {
        const int m0 = rowBase + warp_m + mt * 16 + g;
#pragma unroll
        for (int nt = 0; nt < 8; nt++) {
            const int n0 = colBase + warp_n + nt * 8 + 2 * t;
            float v0 = cr[mt][nt][0], v1 = cr[mt][nt][1];
            float v2 = cr[mt][nt][2], v3 = cr[mt][nt][3];
            if (BIAS) {
                float bb0 = (n0 < N) ? bias[n0] : 0.f;
                float bb1 = (n0 + 1 < N) ? bias[n0 + 1] : 0.f;
                v0 += bb0; v1 += bb1; v2 += bb0; v3 += bb1;
            }
            if (RELU) {
                v0 = fmaxf(v0, 0.f); v1 = fmaxf(v1, 0.f);
                v2 = fmaxf(v2, 0.f); v3 = fmaxf(v3, 0.f);
            }
            if (ROUND) {
                v0 = rtf32(v0); v1 = rtf32(v1);
                v2 = rtf32(v2); v3 = rtf32(v3);
            }
            if (TRANS) {
                if (n0 < N) {
                    if (m0 < M)     C[(size_t)n0 * M + m0] = v0;
                    if (m0 + 8 < M) C[(size_t)n0 * M + m0 + 8] = v2;
                }
                if (n0 + 1 < N) {
                    if (m0 < M)     C[(size_t)(n0 + 1) * M + m0] = v1;
                    if (m0 + 8 < M) C[(size_t)(n0 + 1) * M + m0 + 8] = v3;
                }
            } else {
                if (m0 < M) {
                    if (n0 < N)     C[(size_t)m0 * N + n0] = v0;
                    if (n0 + 1 < N) C[(size_t)m0 * N + n0 + 1] = v1;
                }
                if (m0 + 8 < M) {
                    if (n0 < N)     C[(size_t)(m0 + 8) * N + n0] = v2;
                    if (n0 + 1 < N) C[(size_t)(m0 + 8) * N + n0 + 1] = v3;
                }
            }
        }
    }
}

// ---------------- prep: batched transpose + round weights ------------------
// grid.z selects which (in,out,R,C) pair; per-z guards on grid extent.
__global__ void transpose_round2(const float* __restrict__ in0, float* __restrict__ out0,
                                 int R0, int C0,
                                 const float* __restrict__ in1, float* __restrict__ out1,
                                 int R1, int C1) {
    const float* in = blockIdx.z ? in1 : in0;
    float* out = blockIdx.z ? out1 : out0;
    const int R = blockIdx.z ? R1 : R0;
    const int Cc = blockIdx.z ? C1 : C0;
    int c0 = blockIdx.x * 32, r0 = blockIdx.y * 32;
    if (c0 >= Cc || r0 >= R) return;
    __shared__ float tbuf[32][33];
    int tx = threadIdx.x, ty = threadIdx.y;  // 32x8
#pragma unroll
    for (int j = 0; j < 4; j++) {
        int r = r0 + ty + j * 8, c = c0 + tx;
        tbuf[ty + j * 8][tx] = (r < R && c < Cc) ? in[(size_t)r * Cc + c] : 0.f;
    }
    __syncthreads();
#pragma unroll
    for (int j = 0; j < 4; j++) {
        int c = c0 + ty + j * 8, r = r0 + tx;
        if (c < Cc && r < R) out[(size_t)c * R + r] = rtf32(tbuf[tx][ty + j * 8]);
    }
}

// ---------------- launch ----------------------------------------------------
static inline dim3 gmk(int M, int N) {
    return dim3((unsigned)((N + 127) / 128), (unsigned)((M + 159) / 160), 1);
}

extern "C" void kernel_launch(void* const* d_in, const int* in_sizes, int n_in,
                              void* d_out, int out_size) {
    const float* x   = (const float*)d_in[0];
    const float* adj = (const float*)d_in[1];
    const float* W1  = (const float*)d_in[2];
    const float* b1  = (const float*)d_in[3];
    const float* W2  = (const float*)d_in[4];
    const float* b2  = (const float*)d_in[5];
    const float* W3  = (const float*)d_in[6];
    const float* b3  = (const float*)d_in[7];
    const float* Wf  = (const float*)d_in[8];
    const float* bf  = (const float*)d_in[9];
    float* out = (float*)d_out;

    float *bufA, *bufB, *wts;
    cudaGetSymbolAddress((void**)&bufA, g_bufA);
    cudaGetSymbolAddress((void**)&bufB, g_bufB);
    cudaGetSymbolAddress((void**)&wts, g_wts);

    cudaFuncSetAttribute(tc_gemm<1, 0, 0, 1, 1>, cudaFuncAttributeMaxDynamicSharedMemorySize, SMEM_TOTAL);
    cudaFuncSetAttribute(tc_gemm<1, 0, 0, 1, 0>, cudaFuncAttributeMaxDynamicSharedMemorySize, SMEM_TOTAL);
    cudaFuncSetAttribute(tc_gemm<0, 1, 1, 1, 1>, cudaFuncAttributeMaxDynamicSharedMemorySize, SMEM_TOTAL);
    cudaFuncSetAttribute(tc_gemm<0, 1, 0, 0, 0>, cudaFuncAttributeMaxDynamicSharedMemorySize, SMEM_TOTAL);

    const int M = NNODES;

    // prep: transpose + RNA-round weights (2 batched launches)
    transpose_round2<<<dim3(16, 16, 2), dim3(32, 8)>>>(W1, wts + O_W1T, 512, 512,
                                                       W2, wts + O_W2T, 512, 512);
    transpose_round2<<<dim3(32, 32, 2), dim3(32, 8)>>>(W3, wts + O_W3T, 512, 1024,
                                                       Wf, wts + O_WFT, 1024, 151);

    // F1: bufB = (x @ W1)^T                [512 x 10000]  (x raw -> RNDA)
    tc_gemm<1, 0, 0, 1, 1><<<gmk(M, 512), 128, SMEM_TOTAL>>>(x, wts + O_W1T, nullptr, bufB, M, 512, 512);
    // G1: bufA = relu(adj @ (x@W1) + b1)   [10000 x 512]  (adj raw -> RNDA)
    tc_gemm<0, 1, 1, 1, 1><<<gmk(M, 512), 128, SMEM_TOTAL>>>(adj, bufB, b1, bufA, M, 512, M);
    // F2: A already tf32 (G1 epilogue ROUND)
    tc_gemm<1, 0, 0, 1, 0><<<gmk(M, 512), 128, SMEM_TOTAL>>>(bufA, wts + O_W2T, nullptr, bufB, M, 512, 512);
    // G2
    tc_gemm<0, 1, 1, 1, 1><<<gmk(M, 512), 128, SMEM_TOTAL>>>(adj, bufB, b2, bufA, M, 512, M);
    // F3: bufB = (H2 @ W3)^T               [1024 x 10000]
    tc_gemm<1, 0, 0, 1, 0><<<gmk(M, 1024), 128, SMEM_TOTAL>>>(bufA, wts + O_W3T, nullptr, bufB, M, 1024, 512);
    // G3
    tc_gemm<0, 1, 1, 1, 1><<<gmk(M, 1024), 128, SMEM_TOTAL>>>(adj, bufB, b3, bufA, M, 1024, M);
    // F4: out = H3 @ Wf + bf               [10000 x 151]
    tc_gemm<0, 1, 0, 0, 0><<<gmk(M, 151), 128, SMEM_TOTAL>>>(bufA, wts + O_WFT, bf, out, M, 151, 1024);
}

// round 8
// speedup vs baseline: 1.8817x; 1.8817x over previous
#include <cuda_runtime.h>
#include <cuda_fp16.h>
#include <cstdint>

// GCN via mma.sync FP16 (m16n8k16, fp32 accumulate) + ldmatrix + cp.async.
// fp16 HMMA runs at 2x the tf32 rate with the SAME 11-bit significand, so
// precision matches the tf32 path. adj (uniform[0,1e-4]) is pre-scaled by
// 2^14 into fp16 normal range; the 2^-14 unscale is exact in the G epilogue.
// CTA tile 160x128, KT=64 halves (128-byte rows -> layout/swizzle identical
// to the proven tf32 KT=32 code), 3-stage cp.async pipeline, occ 2.

#define NNODES 10000
#define A_BYTES 20480               // 160 rows x 128 B
#define STAGE_BYTES 36864           // A 20KB + B 16KB
#define SMEM_TOTAL (3 * STAGE_BYTES)

__device__ __half g_adjh[(size_t)NNODES * (size_t)NNODES];
__device__ __half g_bufA[(size_t)NNODES * 1024];
__device__ __half g_bufB[(size_t)NNODES * 1024];
__device__ __half g_wts[1310720];
#define O_W1T 0
#define O_W2T 262144
#define O_W3T 524288
#define O_WFT 1048576

__device__ __forceinline__ uint32_t smem_u32(const void* p) {
    uint32_t a;
    asm("{ .reg .u64 t; cvta.to.shared.u64 t, %1; cvt.u32.u64 %0, t; }"
        : "=r"(a) : "l"(p));
    return a;
}

__device__ __forceinline__ void cpa16(uint32_t dst, const __half* src, int bytes) {
    asm volatile("cp.async.cg.shared.global [%0], [%1], 16, %2;"
                 :: "r"(dst), "l"(src), "r"(bytes) : "memory");
}
#define CP_COMMIT() asm volatile("cp.async.commit_group;" ::: "memory")
#define CP_WAIT1()  asm volatile("cp.async.wait_group 1;" ::: "memory")
#define CP_WAIT0()  asm volatile("cp.async.wait_group 0;" ::: "memory")

__device__ __forceinline__ void ldsm4(uint32_t* r, uint32_t a) {
    asm volatile("ldmatrix.sync.aligned.m8n8.x4.shared.b16 {%0,%1,%2,%3}, [%4];"
                 : "=r"(r[0]), "=r"(r[1]), "=r"(r[2]), "=r"(r[3]) : "r"(a));
}
__device__ __forceinline__ void ldsm2(uint32_t* r, uint32_t a) {
    asm volatile("ldmatrix.sync.aligned.m8n8.x2.shared.b16 {%0,%1}, [%2];"
                 : "=r"(r[0]), "=r"(r[1]) : "r"(a));
}
__device__ __forceinline__ void mma16(float* c, const uint32_t* a, const uint32_t* b) {
    asm volatile("mma.sync.aligned.m16n8k16.row.col.f32.f16.f16.f32 "
                 "{%0,%1,%2,%3}, {%4,%5,%6,%7}, {%8,%9}, {%0,%1,%2,%3};"
                 : "+f"(c[0]), "+f"(c[1]), "+f"(c[2]), "+f"(c[3])
                 : "r"(a[0]), "r"(a[1]), "r"(a[2]), "r"(a[3]),
                   "r"(b[0]), "r"(b[1]));
}

// C = A[M,K] @ B_nk[N,K]^T ; A,B fp16 row-major, leading dim K (halves).
// TRANS: write C^T [N,M]; else [M,N]. SCALE: multiply acc by 2^-14 (adj
// pre-scale undo). OUTF32: fp32 output, else fp16 (RN). CTA tile 160x128.
template <int TRANS, int BIAS, int RELU, int SCALE, int OUTF32>
__global__ void __launch_bounds__(128, 2)
tc_gemm(const __half* __restrict__ A, const __half* __restrict__ B,
        const float* __restrict__ bias, void* __restrict__ Cv,
        int M, int N, int K) {
    extern __shared__ char smem[];
    const uint32_t sb = smem_u32(smem);
    const int tid = threadIdx.x;
    const int lane = tid & 31, w = tid >> 5;
    const int warp_m = (w & 1) * 80, warp_n = (w >> 1) * 64;
    const int rowBase = blockIdx.y * 160, colBase = blockIdx.x * 128;

    // ---- loader: chunk i covers row (tid>>3)+16i, halves (tid&7)*8..+7
    const int ldr = tid >> 3;        // 0..15
    const int ldc8 = (tid & 7) * 8;  // half offset within 64-half chunk
    const uint32_t dstBase = (uint32_t)(ldr * 128) +
                             (uint32_t)(((tid & 7) ^ (ldr & 7)) * 16);
    const __half* aBase = A + (size_t)(rowBase + ldr) * K + ldc8;
    const __half* bBase = B + (size_t)(colBase + ldr) * K + ldc8;
    const size_t K16 = (size_t)K * 16;   // 16-row stride (halves)

    const int nc = (K + 63) >> 6;

    auto issue = [&](int c) {
        const uint32_t st = sb + (uint32_t)(c % 3) * STAGE_BYTES;
        const int k0 = c * 64;
        const bool kok = (k0 + ldc8) < K;
#pragma unroll
        for (int i = 0; i < 10; i++) {  // A: 160 rows
            bool v = kok && (rowBase + ldr + 16 * i) < M;
            cpa16(st + dstBase + (uint32_t)i * 2048,
                  aBase + k0 + (size_t)i * K16, v ? 16 : 0);
        }
#pragma unroll
        for (int i = 0; i < 8; i++) {   // B: 128 rows
            bool v = kok && (colBase + ldr + 16 * i) < N;
            cpa16(st + A_BYTES + dstBase + (uint32_t)i * 2048,
                  bBase + k0 + (size_t)i * K16, v ? 16 : 0);
        }
        CP_COMMIT();
    };

    issue(0);
    issue(1);

    // ---- fragment addressing (identical byte pattern to tf32 version) ----
    const int l8 = lane & 7;
    const int l16 = lane & 15;
    const uint32_t aLdRow = (uint32_t)(warp_m + l8 + ((lane >> 3) & 1) * 8) * 128;
    const uint32_t bLdRow = (uint32_t)(warp_n + (l16 & 7)) * 128;
    uint32_t aChunk[4], bChunk[4];
#pragma unroll
    for (int s = 0; s < 4; s++) {
        aChunk[s] = (uint32_t)(((s * 2 + (lane >> 4)) ^ l8) * 16);
        bChunk[s] = (uint32_t)(((s * 2 + (l16 >> 3)) ^ (l16 & 7)) * 16);
    }

    float cr[5][8][4];
#pragma unroll
    for (int mt = 0; mt < 5; mt++)
#pragma unroll
        for (int nt = 0; nt < 8; nt++)
#pragma unroll
            for (int r = 0; r < 4; r++) cr[mt][nt][r] = 0.f;

    for (int c = 0; c < nc; c++) {
        CP_WAIT1();
        __syncthreads();
        if (c + 2 < nc) issue(c + 2); else CP_COMMIT();

        const uint32_t sA = sb + (uint32_t)(c % 3) * STAGE_BYTES;
        const uint32_t sB = sA + A_BYTES;
#pragma unroll
        for (int s = 0; s < 4; s++) {   // each s-step = k16
            uint32_t a[5][4], b[8][2];
#pragma unroll
            for (int mt = 0; mt < 5; mt++)
                ldsm4(a[mt], sA + aLdRow + mt * 2048 + aChunk[s]);
#pragma unroll
            for (int nt = 0; nt < 8; nt++)
                ldsm2(b[nt], sB + bLdRow + nt * 1024 + bChunk[s]);
#pragma unroll
            for (int mt = 0; mt < 5; mt++)
#pragma unroll
                for (int nt = 0; nt < 8; nt++)
                    mma16(cr[mt][nt], a[mt], b[nt]);
        }
    }
    CP_WAIT0();

    // ---- epilogue ----
    const int g = lane >> 2, t = lane & 3;
#pragma unroll
    for (int mt = 0; mt < 5; mt++) {
        const int m0 = rowBase + warp_m + mt * 16 + g;
#pragma unroll
        for (int nt = 0; nt < 8; nt++) {
            const int n0 = colBase + warp_n + nt * 8 + 2 * t;
            float v0 = cr[mt][nt][0], v1 = cr[mt][nt][1];
            float v2 = cr[mt][nt][2], v3 = cr[mt][nt][3];
            if (SCALE) {   // undo adj pre-scale by 2^14 (exact)
                const float s = 6.103515625e-5f;
                v0 *= s; v1 *= s; v2 *= s; v3 *= s;
            }
            if (BIAS) {
                float bb0 = (n0 < N) ? bias[n0] : 0.f;
                float bb1 = (n0 + 1 < N) ? bias[n0 + 1] : 0.f;
                v0 += bb0; v1 += bb1; v2 += bb0; v3 += bb1;
            }
            if (RELU) {
                v0 = fmaxf(v0, 0.f); v1 = fmaxf(v1, 0.f);
                v2 = fmaxf(v2, 0.f); v3 = fmaxf(v3, 0.f);
            }
            if (OUTF32) {
                float* C = (float*)Cv;
                if (m0 < M) {
                    if (n0 < N)     C[(size_t)m0 * N + n0] = v0;
                    if (n0 + 1 < N) C[(size_t)m0 * N + n0 + 1] = v1;
                }
                if (m0 + 8 < M) {
                    if (n0 < N)     C[(size_t)(m0 + 8) * N + n0] = v2;
                    if (n0 + 1 < N) C[(size_t)(m0 + 8) * N + n0 + 1] = v3;
                }
            } else if (TRANS) {
                __half* C = (__half*)Cv;
                if (n0 < N) {
                    if (m0 < M)     C[(size_t)n0 * M + m0] = __float2half_rn(v0);
                    if (m0 + 8 < M) C[(size_t)n0 * M + m0 + 8] = __float2half_rn(v2);
                }
                if (n0 + 1 < N) {
                    if (m0 < M)     C[(size_t)(n0 + 1) * M + m0] = __float2half_rn(v1);
                    if (m0 + 8 < M) C[(size_t)(n0 + 1) * M + m0 + 8] = __float2half_rn(v3);
                }
            } else {
                __half* C = (__half*)Cv;
                if (m0 < M) {
                    if (n0 < N)     C[(size_t)m0 * N + n0] = __float2half_rn(v0);
                    if (n0 + 1 < N) C[(size_t)m0 * N + n0 + 1] = __float2half_rn(v1);
                }
                if (m0 + 8 < M) {
                    if (n0 < N)     C[(size_t)(m0 + 8) * N + n0] = __float2half_rn(v2);
                    if (n0 + 1 < N) C[(size_t)(m0 + 8) * N + n0 + 1] = __float2half_rn(v3);
                }
            }
        }
    }
}

// ---------------- prep kernels ---------------------------------------------
__global__ void cvt_scale_kernel(const float2* __restrict__ in,
                                 __half2* __restrict__ out, size_t n2, float s) {
    size_t i = (size_t)blockIdx.x * blockDim.x + threadIdx.x;
    size_t stride = (size_t)gridDim.x * blockDim.x;
    for (; i < n2; i += stride) {
        float2 v = in[i];
        out[i] = __floats2half2_rn(v.x * s, v.y * s);
    }
}

// batched transpose + cvt: in[R][Cc] fp32 -> out[Cc][R] fp16
__global__ void transpose_cvt2(const float* __restrict__ in0, __half* __restrict__ out0,
                               int R0, int C0,
                               const float* __restrict__ in1, __half* __restrict__ out1,
                               int R1, int C1) {
    const float* in = blockIdx.z ? in1 : in0;
    __half* out = blockIdx.z ? out1 : out0;
    const int R = blockIdx.z ? R1 : R0;
    const int Cc = blockIdx.z ? C1 : C0;
    int c0 = blockIdx.x * 32, r0 = blockIdx.y * 32;
    if (c0 >= Cc || r0 >= R) return;
    __shared__ float tbuf[32][33];
    int tx = threadIdx.x, ty = threadIdx.y;  // 32x8
#pragma unroll
    for (int j = 0; j < 4; j++) {
        int r = r0 + ty + j * 8, c = c0 + tx;
        tbuf[ty + j * 8][tx] = (r < R && c < Cc) ? in[(size_t)r * Cc + c] : 0.f;
    }
    __syncthreads();
#pragma unroll
    for (int j = 0; j < 4; j++) {
        int c = c0 + ty + j * 8, r = r0 + tx;
        if (c < Cc && r < R) out[(size_t)c * R + r] = __float2half_rn(tbuf[tx][ty + j * 8]);
    }
}

// ---------------- launch ----------------------------------------------------
static inline dim3 gmk(int M, int N) {
    return dim3((unsigned)((N + 127) / 128), (unsigned)((M + 159) / 160), 1);
}

extern "C" void kernel_launch(void* const* d_in, const int* in_sizes, int n_in,
                              void* d_out, int out_size) {
    const float* x   = (const float*)d_in[0];
    const float* adj = (const float*)d_in[1];
    const float* W1  = (const float*)d_in[2];
    const float* b1  = (const float*)d_in[3];
    const float* W2  = (const float*)d_in[4];
    const float* b2  = (const float*)d_in[5];
    const float* W3  = (const float*)d_in[6];
    const float* b3  = (const float*)d_in[7];
    const float* Wf  = (const float*)d_in[8];
    const float* bf  = (const float*)d_in[9];
    float* out = (float*)d_out;

    __half *adjh, *bufA, *bufB, *wts;
    cudaGetSymbolAddress((void**)&adjh, g_adjh);
    cudaGetSymbolAddress((void**)&bufA, g_bufA);
    cudaGetSymbolAddress((void**)&bufB, g_bufB);
    cudaGetSymbolAddress((void**)&wts, g_wts);

    cudaFuncSetAttribute(tc_gemm<1, 0, 0, 0, 0>, cudaFuncAttributeMaxDynamicSharedMemorySize, SMEM_TOTAL);
    cudaFuncSetAttribute(tc_gemm<0, 1, 1, 1, 0>, cudaFuncAttributeMaxDynamicSharedMemorySize, SMEM_TOTAL);
    cudaFuncSetAttribute(tc_gemm<0, 1, 0, 0, 1>, cudaFuncAttributeMaxDynamicSharedMemorySize, SMEM_TOTAL);

    const int M = NNODES;

    // prep: adj -> fp16 scaled by 2^14; x -> fp16; weights transpose+cvt
    cvt_scale_kernel<<<8192, 256>>>((const float2*)adj, (__half2*)adjh,
                                    (size_t)M * M / 2, 16384.f);
    cvt_scale_kernel<<<2048, 256>>>((const float2*)x, (__half2*)bufA,
                                    (size_t)M * 512 / 2, 1.f);
    transpose_cvt2<<<dim3(16, 16, 2), dim3(32, 8)>>>(W1, wts + O_W1T, 512, 512,
                                                     W2, wts + O_W2T, 512, 512);
    transpose_cvt2<<<dim3(32, 32, 2), dim3(32, 8)>>>(W3, wts + O_W3T, 512, 1024,
                                                     Wf, wts + O_WFT, 1024, 151);

    // F1: bufB = (x @ W1)^T                [512 x 10000] fp16
    tc_gemm<1, 0, 0, 0, 0><<<gmk(M, 512), 128, SMEM_TOTAL>>>(bufA, wts + O_W1T, nullptr, bufB, M, 512, 512);
    // G1: bufA = relu(adj @ (x@W1) + b1)   [10000 x 512] fp16 (scaled adj)
    tc_gemm<0, 1, 1, 1, 0><<<gmk(M, 512), 128, SMEM_TOTAL>>>(adjh, bufB, b1, bufA, M, 512, M);
    // F2
    tc_gemm<1, 0, 0, 0, 0><<<gmk(M, 512), 128, SMEM_TOTAL>>>(bufA, wts + O_W2T, nullptr, bufB, M, 512, 512);
    // G2
    tc_gemm<0, 1, 1, 1, 0><<<gmk(M, 512), 128, SMEM_TOTAL>>>(adjh, bufB, b2, bufA, M, 512, M);
    // F3: bufB = (H2 @ W3)^T               [1024 x 10000] fp16
    tc_gemm<1, 0, 0, 0, 0><<<gmk(M, 1024), 128, SMEM_TOTAL>>>(bufA, wts + O_W3T, nullptr, bufB, M, 1024, 512);
    // G3
    tc_gemm<0, 1, 1, 1, 0><<<gmk(M, 1024), 128, SMEM_TOTAL>>>(adjh, bufB, b3, bufA, M, 1024, M);
    // F4: out = H3 @ Wf + bf               [10000 x 151] fp32
    tc_gemm<0, 1, 0, 0, 1><<<gmk(M, 151), 128, SMEM_TOTAL>>>(bufA, wts + O_WFT, bf, out, M, 151, 1024);
}